// round 10
// baseline (speedup 1.0000x reference)
#include <cuda_runtime.h>

// CrossAttMultiplexer collapses analytically:
//   q = x*WQ (outer product with scalar), k = s*WK, scores rank-1,
//   alpha = softmax(scores, axis=-1),
//   out[n,i] = v[n,i] * sum_j alpha[n,i,j] = v[n,i] * 1 = s[n,i] * WV[0]
// The attention cancels entirely; the op is an elementwise scale of s.
// Mandatory traffic: read s (6.29MB) + write out (6.29MB) = 12.6MB.
//
// R10 (final): ten configs (LDG MLP 1-4, bulk-DMA/TMA, streaming hints,
// 384-1536 CTAs, 256-1024 thr) all pin e2e at 6.85-6.88us -> fixed
// launch/replay + ~2us streaming floor. Last untried axis: MINIMUM grid.
// 148 CTAs (1/SM) x 1024 threads, persistent predicated 3-batch,
// front-batched evict-first loads + streaming stores.

#define THREADS 1024
#define BATCH   3
#define NSM     148

__global__ void __launch_bounds__(THREADS)
scale_minigrid_kernel(const float4* __restrict__ s4,
                      const float* __restrict__ WV,
                      float4* __restrict__ out4,
                      int n4) {
    const float wv = __ldg(WV);
    const int stride = gridDim.x * THREADS;          // 151,552
    int idx = blockIdx.x * THREADS + threadIdx.x;

    for (int base = idx; base < n4; base += BATCH * stride) {
        float4 v[BATCH];
        int   id[BATCH];
        bool   p[BATCH];
#pragma unroll
        for (int u = 0; u < BATCH; u++) {
            id[u] = base + u * stride;
            p[u]  = id[u] < n4;
            if (p[u]) v[u] = __ldcs(&s4[id[u]]);     // front-batched loads
        }
#pragma unroll
        for (int u = 0; u < BATCH; u++) {
            if (p[u]) {
                v[u].x *= wv; v[u].y *= wv; v[u].z *= wv; v[u].w *= wv;
                __stcs(&out4[id[u]], v[u]);          // streaming store
            }
        }
    }
}

// Scalar fallback for n not divisible by 4.
__global__ void scale_generic_kernel(const float* __restrict__ s,
                                     const float* __restrict__ WV,
                                     float* __restrict__ out, int n) {
    const float wv = WV[0];
    for (int i = blockIdx.x * blockDim.x + threadIdx.x; i < n;
         i += gridDim.x * blockDim.x)
        out[i] = __ldcs(&s[i]) * wv;
}

extern "C" void kernel_launch(void* const* d_in, const int* in_sizes, int n_in,
                              void* d_out, int out_size) {
    // metadata order: x, s, WQ, WK, WV
    const float* s  = (const float*)d_in[1];
    const float* WV = (const float*)d_in[4];
    float* out = (float*)d_out;

    int n = out_size;                                // 1,572,864 expected
    if ((n & 3) == 0) {
        int n4 = n >> 2;                             // 393,216
        int blocks = NSM;                            // minimum: 1 CTA/SM
        int needed = (n4 + THREADS - 1) / THREADS;
        if (blocks > needed) blocks = needed;        // tiny-input safety
        scale_minigrid_kernel<<<blocks, THREADS>>>((const float4*)s, WV,
                                                   (float4*)out, n4);
    } else {
        int blocks = (n + 255) / 256;
        if (blocks > 1184) blocks = 1184;
        scale_generic_kernel<<<blocks, 256>>>(s, WV, out, n);
    }
}

// round 11
// speedup vs baseline: 1.0337x; 1.0337x over previous
#include <cuda_runtime.h>

// CrossAttMultiplexer collapses analytically:
//   q = x*WQ (outer product with scalar), k = s*WK  ->  scores rank-1:
//   scores[n,i,j] = (WQ.WK)/sqrt(d) * x[n,i] * s[n,j]
//   alpha = softmax(scores, axis=-1)
//   out[n,i] = v[n,i] * sum_j alpha[n,i,j] = v[n,i] * 1 = s[n,i] * WV[0]
// The attention cancels entirely; the op is an elementwise scale of s.
// Mandatory traffic: read s (6.29MB) + write out (6.29MB) = 12.6MB.
//
// R11 (final commit): 11 configs spanning LDG MLP 1-4, bulk-DMA/TMA,
// cache hints, 148-1536 CTAs, 256-1024 threads all pin e2e at 6.85-6.88us
// -> fixed launch/replay overhead + ~2us irreducible streaming. The real
// speedup is the analytic collapse above (~1000x work reduction vs the
// reference's (N,96,96) softmax).
//
// Last untested cell of the cache-hint matrix: DEFAULT loads (s is re-read
// every timed replay -> keep L2-resident) + STREAMING stores (out has zero
// read reuse -> evict-first, don't displace s). Exact-tile straight-line
// body with the best-measured shape: 768 CTAs x 256 thr x 2 float4.

#define THREADS 256
#define BATCH   2

__global__ void __launch_bounds__(THREADS)
scale_final_kernel(const float4* __restrict__ s4,
                   const float* __restrict__ WV,
                   float4* __restrict__ out4) {
    const float wv = __ldg(WV);
    int base = blockIdx.x * (THREADS * BATCH) + threadIdx.x;

    float4 v[BATCH];
#pragma unroll
    for (int u = 0; u < BATCH; u++)
        v[u] = s4[base + u * THREADS];            // default cache: L2-resident
#pragma unroll
    for (int u = 0; u < BATCH; u++) {
        v[u].x *= wv; v[u].y *= wv; v[u].z *= wv; v[u].w *= wv;
        __stcs(&out4[base + u * THREADS], v[u]);  // streaming: evict-first
    }
}

// Generic fallback (bounds-checked, grid-stride) for sizes that don't tile.
__global__ void scale_generic_kernel(const float* __restrict__ s,
                                     const float* __restrict__ WV,
                                     float* __restrict__ out, int n) {
    const float wv = WV[0];
    for (int i = blockIdx.x * blockDim.x + threadIdx.x; i < n;
         i += gridDim.x * blockDim.x)
        out[i] = s[i] * wv;
}

extern "C" void kernel_launch(void* const* d_in, const int* in_sizes, int n_in,
                              void* d_out, int out_size) {
    // metadata order: x, s, WQ, WK, WV
    const float* s  = (const float*)d_in[1];
    const float* WV = (const float*)d_in[4];
    float* out = (float*)d_out;

    int n = out_size;                              // 1,572,864 expected
    const int tile = THREADS * BATCH * 4;          // 2048 elements per CTA
    if ((n % tile) == 0) {
        int blocks = n / tile;                     // 768
        scale_final_kernel<<<blocks, THREADS>>>((const float4*)s, WV,
                                                (float4*)out);
    } else {
        int blocks = (n + 255) / 256;
        if (blocks > 1184) blocks = 1184;
        scale_generic_kernel<<<blocks, 256>>>(s, WV, out, n);
    }
}